// round 4
// baseline (speedup 1.0000x reference)
#include <cuda_runtime.h>

#define ED 2048
#define NH 16
#define HD 128
#define LCACHE 8192
#define L1 8193

// scratch (no allocs allowed)
__device__ float g_q[ED];
__device__ float g_scores[NH * L1];
__device__ float g_hmax[NH];
__device__ float g_hsum[NH];
__device__ float g_vals[ED];

// ---------------------------------------------------------------------------
// Kernel A: three GEMVs x@W + b for q, k, v.  96 blocks x 256 threads.
// m = block/32 selects matrix; each block computes 64 output columns.
// q -> g_q ; k_i -> out_k tail row ; v_i -> out_v tail row.
// ---------------------------------------------------------------------------
__global__ void proj_kernel(const float* __restrict__ x,
                            const float* __restrict__ Wq, const float* __restrict__ bq,
                            const float* __restrict__ Wk, const float* __restrict__ bk,
                            const float* __restrict__ Wv, const float* __restrict__ bv,
                            float* __restrict__ out_k_tail,
                            float* __restrict__ out_v_tail) {
    __shared__ float sx[ED];
    __shared__ float red[4][64];
    int t = threadIdx.x;
    for (int i = t; i < ED; i += 256) sx[i] = x[i];
    __syncthreads();

    int m  = blockIdx.x >> 5;            // 0=q, 1=k, 2=v
    int jb = (blockIdx.x & 31) * 64;
    const float* W = (m == 0) ? Wq : (m == 1) ? Wk : Wv;
    const float* b = (m == 0) ? bq : (m == 1) ? bk : bv;

    int j    = jb + (t & 63);
    int isub = t >> 6;                   // 0..3
    float acc = 0.f;
    for (int i = isub; i < ED; i += 4)
        acc += sx[i] * W[(size_t)i * ED + j];
    red[isub][t & 63] = acc;
    __syncthreads();
    if (t < 64) {
        float r = red[0][t] + red[1][t] + red[2][t] + red[3][t] + b[jb + t];
        float* dst = (m == 0) ? g_q : (m == 1) ? out_k_tail : out_v_tail;
        dst[jb + t] = r;
    }
}

// ---------------------------------------------------------------------------
// Kernel B: scores[h][l] = (q_h . k[l,h]) * scale for l in [0, 8193),
// fused with K-cache copy to output.  129 blocks x 256 threads, 64 rows/block.
// Thread t owns float4 columns 4t (head t/32... = warp id) and 1024+4t
// (head warp+8); warp-shuffle reduces each head's 128-wide dot product.
// Row 8192 reads k_i from the output tail (written by kernel A).
// ---------------------------------------------------------------------------
__global__ void score_copyk_kernel(const float* __restrict__ kc,
                                   float* __restrict__ out_k,
                                   float scale) {
    int t = threadIdx.x;
    int w = t >> 5;
    int l0 = blockIdx.x * 64;
    int nrows = min(64, L1 - l0);

    float4 q0 = ((const float4*)g_q)[t];
    float4 q1 = ((const float4*)g_q)[256 + t];

    for (int r = 0; r < nrows; ++r) {
        int l = l0 + r;
        const float4* src = (l < LCACHE)
            ? (const float4*)(kc + (size_t)l * ED)
            : (const float4*)(out_k + (size_t)LCACHE * ED);
        float4 a = src[t];
        float4 c = src[256 + t];
        if (l < LCACHE) {
            float4* d = (float4*)(out_k + (size_t)l * ED);
            d[t] = a;
            d[256 + t] = c;
        }
        float d0 = a.x * q0.x + a.y * q0.y + a.z * q0.z + a.w * q0.w;
        float d1 = c.x * q1.x + c.y * q1.y + c.z * q1.z + c.w * q1.w;
        #pragma unroll
        for (int off = 16; off; off >>= 1) {
            d0 += __shfl_xor_sync(0xffffffff, d0, off);
            d1 += __shfl_xor_sync(0xffffffff, d1, off);
        }
        if ((t & 31) == 0) {
            g_scores[(size_t)w * L1 + l]       = d0 * scale;
            g_scores[(size_t)(w + 8) * L1 + l] = d1 * scale;
        }
    }
}

// ---------------------------------------------------------------------------
// Kernel C: per-head softmax statistics (max, sum of exp). 16 blocks.
// Also zeroes the g_vals accumulator for kernel D's atomics.
// ---------------------------------------------------------------------------
__global__ void softmax_stats_kernel() {
    int h = blockIdx.x, t = threadIdx.x;
    __shared__ float red[256];
    const float* s = g_scores + (size_t)h * L1;

    float m = -1e30f;
    for (int i = t; i < L1; i += 256) m = fmaxf(m, s[i]);
    red[t] = m; __syncthreads();
    for (int o = 128; o; o >>= 1) {
        if (t < o) red[t] = fmaxf(red[t], red[t + o]);
        __syncthreads();
    }
    float mx = red[0];
    __syncthreads();

    float sum = 0.f;
    for (int i = t; i < L1; i += 256) sum += expf(s[i] - mx);
    red[t] = sum; __syncthreads();
    for (int o = 128; o; o >>= 1) {
        if (t < o) red[t] += red[t + o];
        __syncthreads();
    }
    if (t == 0) { g_hmax[h] = mx; g_hsum[h] = red[0]; }
    if (t < HD) g_vals[h * HD + t] = 0.f;
}

// ---------------------------------------------------------------------------
// Kernel D: values[h][d] = sum_l p[h][l] * v[l,h,d], fused with V-cache copy.
// Same column ownership as kernel B. Softmax probs for the 64-row chunk are
// staged in shared; per-block partial sums land in g_vals via atomicAdd.
// ---------------------------------------------------------------------------
__global__ void av_copyv_kernel(const float* __restrict__ vc,
                                float* __restrict__ out_v) {
    int t = threadIdx.x;
    int l0 = blockIdx.x * 64;
    int nrows = min(64, L1 - l0);

    __shared__ float sp[64][16];
    __shared__ float smx[16], sinv[16];
    if (t < 16) { smx[t] = g_hmax[t]; sinv[t] = 1.f / g_hsum[t]; }
    __syncthreads();
    for (int idx = t; idx < nrows * 16; idx += 256) {
        int r = idx >> 4, h = idx & 15;
        sp[r][h] = expf(g_scores[(size_t)h * L1 + l0 + r] - smx[h]) * sinv[h];
    }
    __syncthreads();

    int h0 = t >> 5, h1 = h0 + 8;
    float a0 = 0, a1 = 0, a2 = 0, a3 = 0;
    float b0 = 0, b1 = 0, b2 = 0, b3 = 0;
    for (int r = 0; r < nrows; ++r) {
        int l = l0 + r;
        const float4* src = (l < LCACHE)
            ? (const float4*)(vc + (size_t)l * ED)
            : (const float4*)(out_v + (size_t)LCACHE * ED);
        float4 a = src[t];
        float4 c = src[256 + t];
        if (l < LCACHE) {
            float4* d = (float4*)(out_v + (size_t)l * ED);
            d[t] = a;
            d[256 + t] = c;
        }
        float p0 = sp[r][h0], p1 = sp[r][h1];
        a0 += p0 * a.x; a1 += p0 * a.y; a2 += p0 * a.z; a3 += p0 * a.w;
        b0 += p1 * c.x; b1 += p1 * c.y; b2 += p1 * c.z; b3 += p1 * c.w;
    }
    int c0 = 4 * t, c1 = 1024 + 4 * t;
    atomicAdd(&g_vals[c0],     a0);
    atomicAdd(&g_vals[c0 + 1], a1);
    atomicAdd(&g_vals[c0 + 2], a2);
    atomicAdd(&g_vals[c0 + 3], a3);
    atomicAdd(&g_vals[c1],     b0);
    atomicAdd(&g_vals[c1 + 1], b1);
    atomicAdd(&g_vals[c1 + 2], b2);
    atomicAdd(&g_vals[c1 + 3], b3);
}

// ---------------------------------------------------------------------------
// Kernel E: out_i = g_vals @ Wo + bo.  32 blocks x 256 threads.
// ---------------------------------------------------------------------------
__global__ void out_proj_kernel(const float* __restrict__ Wo,
                                const float* __restrict__ bo,
                                float* __restrict__ out_i) {
    __shared__ float sx[ED];
    __shared__ float red[4][64];
    int t = threadIdx.x;
    for (int i = t; i < ED; i += 256) sx[i] = g_vals[i];
    __syncthreads();

    int jb = blockIdx.x * 64;
    int j = jb + (t & 63);
    int isub = t >> 6;
    float acc = 0.f;
    for (int i = isub; i < ED; i += 4)
        acc += sx[i] * Wo[(size_t)i * ED + j];
    red[isub][t & 63] = acc;
    __syncthreads();
    if (t < 64)
        out_i[jb + t] = red[0][t] + red[1][t] + red[2][t] + red[3][t] + bo[jb + t];
}

extern "C" void kernel_launch(void* const* d_in, const int* in_sizes, int n_in,
                              void* d_out, int out_size) {
    const float* x  = (const float*)d_in[0];
    const float* v  = (const float*)d_in[1];
    const float* k  = (const float*)d_in[2];
    const float* Wv = (const float*)d_in[3];
    const float* bv = (const float*)d_in[4];
    const float* Wq = (const float*)d_in[5];
    const float* bq = (const float*)d_in[6];
    const float* Wk = (const float*)d_in[7];
    const float* bk = (const float*)d_in[8];
    const float* Wo = (const float*)d_in[9];
    const float* bo = (const float*)d_in[10];

    float* out   = (float*)d_out;
    float* out_i = out;                               // [2048]
    float* out_v = out + ED;                          // [8193, 2048]
    float* out_k = out_v + (size_t)L1 * ED;           // [8193, 2048]

    proj_kernel<<<96, 256>>>(x, Wq, bq, Wk, bk, Wv, bv,
                             out_k + (size_t)LCACHE * ED,
                             out_v + (size_t)LCACHE * ED);
    score_copyk_kernel<<<129, 256>>>(k, out_k, 0.08838834764831845f);
    softmax_stats_kernel<<<16, 256>>>();
    av_copyv_kernel<<<129, 256>>>(v, out_v);
    out_proj_kernel<<<32, 256>>>(Wo, bo, out_i);
}

// round 5
// speedup vs baseline: 1.9791x; 1.9791x over previous
#include <cuda_runtime.h>

#define ED 2048
#define NH 16
#define HD 128
#define LCACHE 8192
#define L1 8193

// scratch (no allocs allowed)
__device__ float g_q[ED];
__device__ float g_scores[NH * L1];
__device__ float g_hsum[NH];
__device__ float g_vals[ED];

// ---------------------------------------------------------------------------
// Kernel A: three GEMVs x@W + b for q, k, v.  192 blocks x 256 threads.
// m = block/64 selects matrix; each block computes 32 output columns with
// 8 i-slices and 4-way unroll (4 independent loads in flight per thread).
// Block 0 also zeroes g_hsum for kernel B's atomic exp-sums.
// ---------------------------------------------------------------------------
__global__ void proj_kernel(const float* __restrict__ x,
                            const float* __restrict__ Wq, const float* __restrict__ bq,
                            const float* __restrict__ Wk, const float* __restrict__ bk,
                            const float* __restrict__ Wv, const float* __restrict__ bv,
                            float* __restrict__ out_k_tail,
                            float* __restrict__ out_v_tail) {
    __shared__ float sx[ED];
    __shared__ float red[8][32];
    int t = threadIdx.x;
    for (int i = t; i < ED; i += 256) sx[i] = x[i];
    if (blockIdx.x == 0 && t < NH) g_hsum[t] = 0.f;
    __syncthreads();

    int m  = blockIdx.x / 64;            // 0=q, 1=k, 2=v
    int jb = (blockIdx.x % 64) * 32;
    const float* W = (m == 0) ? Wq : (m == 1) ? Wk : Wv;
    const float* b = (m == 0) ? bq : (m == 1) ? bk : bv;

    int j    = jb + (t & 31);
    int isub = t >> 5;                   // 0..7
    float a0 = 0.f, a1 = 0.f, a2 = 0.f, a3 = 0.f;
    for (int i = isub; i < ED; i += 32) {
        a0 += sx[i]      * W[(size_t)i * ED + j];
        a1 += sx[i + 8]  * W[(size_t)(i + 8) * ED + j];
        a2 += sx[i + 16] * W[(size_t)(i + 16) * ED + j];
        a3 += sx[i + 24] * W[(size_t)(i + 24) * ED + j];
    }
    red[isub][t & 31] = (a0 + a1) + (a2 + a3);
    __syncthreads();
    if (t < 32) {
        float r = b[jb + t];
        #pragma unroll
        for (int s = 0; s < 8; ++s) r += red[s][t];
        float* dst = (m == 0) ? g_q : (m == 1) ? out_k_tail : out_v_tail;
        dst[jb + t] = r;
    }
}

// ---------------------------------------------------------------------------
// Kernel B: scores for rows [0,8192) fused with K-cache copy.
// 512 blocks x 512 threads, 16 rows/block. Warp w owns head w (lane's float4
// = cols 4t..4t+3, warp covers exactly 128 cols). 4-row manual unroll.
// Max-free softmax: per-warp exp-sums accumulate into g_hsum via atomics.
// ---------------------------------------------------------------------------
__global__ void score_copyk_kernel(const float* __restrict__ kc,
                                   float* __restrict__ out_k,
                                   float scale) {
    int t = threadIdx.x;
    int h = t >> 5;
    int lane = t & 31;
    int l0 = blockIdx.x * 16;

    float4 q = ((const float4*)g_q)[t];
    const float4* src = (const float4*)(kc + (size_t)l0 * ED);
    float4*       dst = (float4*)(out_k + (size_t)l0 * ED);

    float lsum = 0.f;
    #pragma unroll
    for (int r0 = 0; r0 < 16; r0 += 4) {
        float4 a0 = __ldcs(&src[(r0 + 0) * 512 + t]);
        float4 a1 = __ldcs(&src[(r0 + 1) * 512 + t]);
        float4 a2 = __ldcs(&src[(r0 + 2) * 512 + t]);
        float4 a3 = __ldcs(&src[(r0 + 3) * 512 + t]);
        __stcs(&dst[(r0 + 0) * 512 + t], a0);
        __stcs(&dst[(r0 + 1) * 512 + t], a1);
        __stcs(&dst[(r0 + 2) * 512 + t], a2);
        __stcs(&dst[(r0 + 3) * 512 + t], a3);
        float d0 = a0.x * q.x + a0.y * q.y + a0.z * q.z + a0.w * q.w;
        float d1 = a1.x * q.x + a1.y * q.y + a1.z * q.z + a1.w * q.w;
        float d2 = a2.x * q.x + a2.y * q.y + a2.z * q.z + a2.w * q.w;
        float d3 = a3.x * q.x + a3.y * q.y + a3.z * q.z + a3.w * q.w;
        #pragma unroll
        for (int off = 16; off; off >>= 1) {
            d0 += __shfl_xor_sync(0xffffffff, d0, off);
            d1 += __shfl_xor_sync(0xffffffff, d1, off);
            d2 += __shfl_xor_sync(0xffffffff, d2, off);
            d3 += __shfl_xor_sync(0xffffffff, d3, off);
        }
        if (lane == 0) {
            float s0 = d0 * scale, s1 = d1 * scale, s2 = d2 * scale, s3 = d3 * scale;
            float* sc = g_scores + (size_t)h * L1 + l0 + r0;
            sc[0] = s0; sc[1] = s1; sc[2] = s2; sc[3] = s3;
            lsum += (expf(s0) + expf(s1)) + (expf(s2) + expf(s3));
        }
    }
    if (lane == 0) atomicAdd(&g_hsum[h], lsum);
}

// ---------------------------------------------------------------------------
// Kernel C (tiny): handle the appended row l=8192 per head.
// Computes tail score, finalizes g_hsum (+= exp), and initializes g_vals
// with the tail's softmax-weighted V contribution.  16 blocks x 128 threads.
// ---------------------------------------------------------------------------
__global__ void tail_kernel(const float* __restrict__ out_k_tail,
                            const float* __restrict__ out_v_tail,
                            float scale) {
    int h = blockIdx.x, t = threadIdx.x;
    __shared__ float red[128];
    __shared__ float s_p;
    red[t] = g_q[h * HD + t] * out_k_tail[h * HD + t];
    __syncthreads();
    #pragma unroll
    for (int o = 64; o; o >>= 1) {
        if (t < o) red[t] += red[t + o];
        __syncthreads();
    }
    if (t == 0) {
        float e = expf(red[0] * scale);
        float tot = g_hsum[h] + e;
        g_hsum[h] = tot;
        s_p = e / tot;
    }
    __syncthreads();
    g_vals[h * HD + t] = s_p * out_v_tail[h * HD + t];
}

// ---------------------------------------------------------------------------
// Kernel D: values += sum_l p[h][l] * v[l,h,:], fused with V-cache copy.
// 256 blocks x 512 threads, 32 rows/block, warp==head, 4-row unroll.
// Probs staged in shared; per-block partials land in g_vals via atomicAdd.
// ---------------------------------------------------------------------------
__global__ void av_copyv_kernel(const float* __restrict__ vc,
                                float* __restrict__ out_v) {
    int t = threadIdx.x;
    int h = t >> 5;
    int l0 = blockIdx.x * 32;

    __shared__ float sinv[NH];
    __shared__ float sp[32][NH + 1];
    if (t < NH) sinv[t] = 1.f / g_hsum[t];
    __syncthreads();
    for (int idx = t; idx < 32 * NH; idx += 512) {
        int r = idx >> 4, hh = idx & 15;
        sp[r][hh] = expf(g_scores[(size_t)hh * L1 + l0 + r]) * sinv[hh];
    }
    __syncthreads();

    const float4* src = (const float4*)(vc + (size_t)l0 * ED);
    float4*       dst = (float4*)(out_v + (size_t)l0 * ED);

    float cx = 0.f, cy = 0.f, cz = 0.f, cw = 0.f;
    #pragma unroll 4
    for (int r0 = 0; r0 < 32; r0 += 4) {
        float4 a0 = __ldcs(&src[(r0 + 0) * 512 + t]);
        float4 a1 = __ldcs(&src[(r0 + 1) * 512 + t]);
        float4 a2 = __ldcs(&src[(r0 + 2) * 512 + t]);
        float4 a3 = __ldcs(&src[(r0 + 3) * 512 + t]);
        __stcs(&dst[(r0 + 0) * 512 + t], a0);
        __stcs(&dst[(r0 + 1) * 512 + t], a1);
        __stcs(&dst[(r0 + 2) * 512 + t], a2);
        __stcs(&dst[(r0 + 3) * 512 + t], a3);
        float p0 = sp[r0 + 0][h], p1 = sp[r0 + 1][h];
        float p2 = sp[r0 + 2][h], p3 = sp[r0 + 3][h];
        cx += p0 * a0.x + p1 * a1.x + p2 * a2.x + p3 * a3.x;
        cy += p0 * a0.y + p1 * a1.y + p2 * a2.y + p3 * a3.y;
        cz += p0 * a0.z + p1 * a1.z + p2 * a2.z + p3 * a3.z;
        cw += p0 * a0.w + p1 * a1.w + p2 * a2.w + p3 * a3.w;
    }
    int c = 4 * t;
    atomicAdd(&g_vals[c],     cx);
    atomicAdd(&g_vals[c + 1], cy);
    atomicAdd(&g_vals[c + 2], cz);
    atomicAdd(&g_vals[c + 3], cw);
}

// ---------------------------------------------------------------------------
// Kernel E: out_i = g_vals @ Wo + bo.  64 blocks x 256 threads, 32 cols/block.
// ---------------------------------------------------------------------------
__global__ void out_proj_kernel(const float* __restrict__ Wo,
                                const float* __restrict__ bo,
                                float* __restrict__ out_i) {
    __shared__ float sx[ED];
    __shared__ float red[8][32];
    int t = threadIdx.x;
    for (int i = t; i < ED; i += 256) sx[i] = g_vals[i];
    __syncthreads();

    int jb = blockIdx.x * 32;
    int j = jb + (t & 31);
    int isub = t >> 5;
    float a0 = 0.f, a1 = 0.f, a2 = 0.f, a3 = 0.f;
    for (int i = isub; i < ED; i += 32) {
        a0 += sx[i]      * Wo[(size_t)i * ED + j];
        a1 += sx[i + 8]  * Wo[(size_t)(i + 8) * ED + j];
        a2 += sx[i + 16] * Wo[(size_t)(i + 16) * ED + j];
        a3 += sx[i + 24] * Wo[(size_t)(i + 24) * ED + j];
    }
    red[isub][t & 31] = (a0 + a1) + (a2 + a3);
    __syncthreads();
    if (t < 32) {
        float r = bo[jb + t];
        #pragma unroll
        for (int s = 0; s < 8; ++s) r += red[s][t];
        out_i[jb + t] = r;
    }
}

extern "C" void kernel_launch(void* const* d_in, const int* in_sizes, int n_in,
                              void* d_out, int out_size) {
    const float* x  = (const float*)d_in[0];
    const float* v  = (const float*)d_in[1];
    const float* k  = (const float*)d_in[2];
    const float* Wv = (const float*)d_in[3];
    const float* bv = (const float*)d_in[4];
    const float* Wq = (const float*)d_in[5];
    const float* bq = (const float*)d_in[6];
    const float* Wk = (const float*)d_in[7];
    const float* bk = (const float*)d_in[8];
    const float* Wo = (const float*)d_in[9];
    const float* bo = (const float*)d_in[10];

    float* out   = (float*)d_out;
    float* out_i = out;                               // [2048]
    float* out_v = out + ED;                          // [8193, 2048]
    float* out_k = out_v + (size_t)L1 * ED;           // [8193, 2048]
    float* k_tail = out_k + (size_t)LCACHE * ED;
    float* v_tail = out_v + (size_t)LCACHE * ED;
    const float scale = 0.08838834764831845f;

    proj_kernel<<<192, 256>>>(x, Wq, bq, Wk, bk, Wv, bv, k_tail, v_tail);
    score_copyk_kernel<<<512, 512>>>(k, out_k, scale);
    tail_kernel<<<16, 128>>>(k_tail, v_tail, scale);
    av_copyv_kernel<<<256, 512>>>(v, out_v);
    out_proj_kernel<<<64, 256>>>(Wo, bo, out_i);
}

// round 7
// speedup vs baseline: 2.4164x; 1.2210x over previous
#include <cuda_runtime.h>

#define ED 2048
#define NH 16
#define HD 128
#define LCACHE 8192
#define L1 8193

// scratch (no allocs allowed)
__device__ float g_q[ED];
__device__ float g_scores[NH * L1];
__device__ float g_hsum[NH];
__device__ float g_vals[ED];

// ---------------------------------------------------------------------------
// Kernel A: three GEMVs x@W + b for q, k, v.  384 blocks x 256 threads.
// m = block/128 selects matrix; each block computes 16 output columns with
// 16 i-slices and 4-way unroll (4 independent loads in flight per thread).
// Block 0 also zeroes g_hsum for kernel B's atomic exp-sums.
// ---------------------------------------------------------------------------
__global__ void __launch_bounds__(256, 8)
proj_kernel(const float* __restrict__ x,
            const float* __restrict__ Wq, const float* __restrict__ bq,
            const float* __restrict__ Wk, const float* __restrict__ bk,
            const float* __restrict__ Wv, const float* __restrict__ bv,
            float* __restrict__ out_k_tail,
            float* __restrict__ out_v_tail) {
    __shared__ float sx[ED];
    __shared__ float red[16][16];
    int t = threadIdx.x;
    for (int i = t; i < ED; i += 256) sx[i] = x[i];
    if (blockIdx.x == 0 && t < NH) g_hsum[t] = 0.f;
    __syncthreads();

    int m  = blockIdx.x >> 7;            // 0=q, 1=k, 2=v
    int jb = (blockIdx.x & 127) * 16;
    const float* W = (m == 0) ? Wq : (m == 1) ? Wk : Wv;
    const float* b = (m == 0) ? bq : (m == 1) ? bk : bv;

    int j    = jb + (t & 15);
    int isub = t >> 4;                   // 0..15
    float a0 = 0.f, a1 = 0.f, a2 = 0.f, a3 = 0.f;
    for (int i = isub; i < ED; i += 64) {
        a0 += sx[i]      * W[(size_t)i * ED + j];
        a1 += sx[i + 16] * W[(size_t)(i + 16) * ED + j];
        a2 += sx[i + 32] * W[(size_t)(i + 32) * ED + j];
        a3 += sx[i + 48] * W[(size_t)(i + 48) * ED + j];
    }
    red[isub][t & 15] = (a0 + a1) + (a2 + a3);
    __syncthreads();
    if (t < 16) {
        float r = b[jb + t];
        #pragma unroll
        for (int s = 0; s < 16; ++s) r += red[s][t];
        float* dst = (m == 0) ? g_q : (m == 1) ? out_k_tail : out_v_tail;
        dst[jb + t] = r;
    }
}

// ---------------------------------------------------------------------------
// Kernel B: scores for rows [0,8192) fused with K-cache copy.
// 256 blocks x 512 threads, 32 rows/block in 8-row batches (8 independent
// LDG.128 in flight per thread).  Warp w owns head w.  Max-free softmax:
// per-warp exp-sums accumulate into g_hsum via atomics.
// ---------------------------------------------------------------------------
__global__ void __launch_bounds__(512, 2)
score_copyk_kernel(const float* __restrict__ kc,
                   float* __restrict__ out_k,
                   float scale) {
    int t = threadIdx.x;
    int h = t >> 5;
    int lane = t & 31;
    int l0 = blockIdx.x * 32;

    float4 q = ((const float4*)g_q)[t];
    const float4* src = (const float4*)(kc + (size_t)l0 * ED);
    float4*       dst = (float4*)(out_k + (size_t)l0 * ED);

    float lsum = 0.f;
    #pragma unroll
    for (int r0 = 0; r0 < 32; r0 += 8) {
        float4 a[8];
        #pragma unroll
        for (int u = 0; u < 8; ++u) a[u] = __ldcs(&src[(r0 + u) * 512 + t]);
        #pragma unroll
        for (int u = 0; u < 8; ++u) __stcs(&dst[(r0 + u) * 512 + t], a[u]);
        float d[8];
        #pragma unroll
        for (int u = 0; u < 8; ++u)
            d[u] = a[u].x * q.x + a[u].y * q.y + a[u].z * q.z + a[u].w * q.w;
        #pragma unroll
        for (int off = 16; off; off >>= 1) {
            #pragma unroll
            for (int u = 0; u < 8; ++u)
                d[u] += __shfl_xor_sync(0xffffffff, d[u], off);
        }
        if (lane == 0) {
            float* sc = g_scores + (size_t)h * L1 + l0 + r0;
            #pragma unroll
            for (int u = 0; u < 8; ++u) {
                float s = d[u] * scale;
                sc[u] = s;
                lsum += expf(s);
            }
        }
    }
    if (lane == 0) atomicAdd(&g_hsum[h], lsum);
}

// ---------------------------------------------------------------------------
// Kernel C (tiny): handle the appended row l=8192 per head.
// Computes tail score, finalizes g_hsum (+= exp), and initializes g_vals
// with the tail's softmax-weighted V contribution.  16 blocks x 128 threads.
// ---------------------------------------------------------------------------
__global__ void tail_kernel(const float* __restrict__ out_k_tail,
                            const float* __restrict__ out_v_tail,
                            float scale) {
    int h = blockIdx.x, t = threadIdx.x;
    __shared__ float red[128];
    __shared__ float s_p;
    red[t] = g_q[h * HD + t] * out_k_tail[h * HD + t];
    __syncthreads();
    #pragma unroll
    for (int o = 64; o; o >>= 1) {
        if (t < o) red[t] += red[t + o];
        __syncthreads();
    }
    if (t == 0) {
        float e = expf(red[0] * scale);
        float tot = g_hsum[h] + e;
        g_hsum[h] = tot;
        s_p = e / tot;
    }
    __syncthreads();
    g_vals[h * HD + t] = s_p * out_v_tail[h * HD + t];
}

// ---------------------------------------------------------------------------
// Kernel D: values += sum_l p[h][l] * v[l,h,:], fused with V-cache copy.
// 256 blocks x 512 threads, 32 rows/block in 8-row batches, warp==head.
// Probs staged in shared; per-block partials land in g_vals via atomicAdd.
// ---------------------------------------------------------------------------
__global__ void __launch_bounds__(512, 2)
av_copyv_kernel(const float* __restrict__ vc,
                float* __restrict__ out_v) {
    int t = threadIdx.x;
    int h = t >> 5;
    int l0 = blockIdx.x * 32;

    __shared__ float sinv[NH];
    __shared__ float sp[32][NH + 1];
    if (t < NH) sinv[t] = 1.f / g_hsum[t];
    __syncthreads();
    for (int idx = t; idx < 32 * NH; idx += 512) {
        int r = idx >> 4, hh = idx & 15;
        sp[r][hh] = expf(g_scores[(size_t)hh * L1 + l0 + r]) * sinv[hh];
    }
    __syncthreads();

    const float4* src = (const float4*)(vc + (size_t)l0 * ED);
    float4*       dst = (float4*)(out_v + (size_t)l0 * ED);

    float cx = 0.f, cy = 0.f, cz = 0.f, cw = 0.f;
    #pragma unroll
    for (int r0 = 0; r0 < 32; r0 += 8) {
        float4 a[8];
        #pragma unroll
        for (int u = 0; u < 8; ++u) a[u] = __ldcs(&src[(r0 + u) * 512 + t]);
        #pragma unroll
        for (int u = 0; u < 8; ++u) __stcs(&dst[(r0 + u) * 512 + t], a[u]);
        #pragma unroll
        for (int u = 0; u < 8; ++u) {
            float p = sp[r0 + u][h];
            cx += p * a[u].x;
            cy += p * a[u].y;
            cz += p * a[u].z;
            cw += p * a[u].w;
        }
    }
    int c = 4 * t;
    atomicAdd(&g_vals[c],     cx);
    atomicAdd(&g_vals[c + 1], cy);
    atomicAdd(&g_vals[c + 2], cz);
    atomicAdd(&g_vals[c + 3], cw);
}

// ---------------------------------------------------------------------------
// Kernel E: out_i = g_vals @ Wo + bo.  128 blocks x 256 threads, 16 cols/block.
// ---------------------------------------------------------------------------
__global__ void __launch_bounds__(256, 8)
out_proj_kernel(const float* __restrict__ Wo,
                const float* __restrict__ bo,
                float* __restrict__ out_i) {
    __shared__ float sx[ED];
    __shared__ float red[16][16];
    int t = threadIdx.x;
    for (int i = t; i < ED; i += 256) sx[i] = g_vals[i];
    __syncthreads();

    int jb = blockIdx.x * 16;
    int j = jb + (t & 15);
    int isub = t >> 4;
    float a0 = 0.f, a1 = 0.f, a2 = 0.f, a3 = 0.f;
    for (int i = isub; i < ED; i += 64) {
        a0 += sx[i]      * Wo[(size_t)i * ED + j];
        a1 += sx[i + 16] * Wo[(size_t)(i + 16) * ED + j];
        a2 += sx[i + 32] * Wo[(size_t)(i + 32) * ED + j];
        a3 += sx[i + 48] * Wo[(size_t)(i + 48) * ED + j];
    }
    red[isub][t & 15] = (a0 + a1) + (a2 + a3);
    __syncthreads();
    if (t < 16) {
        float r = bo[jb + t];
        #pragma unroll
        for (int s = 0; s < 16; ++s) r += red[s][t];
        out_i[jb + t] = r;
    }
}

extern "C" void kernel_launch(void* const* d_in, const int* in_sizes, int n_in,
                              void* d_out, int out_size) {
    const float* x  = (const float*)d_in[0];
    const float* v  = (const float*)d_in[1];
    const float* k  = (const float*)d_in[2];
    const float* Wv = (const float*)d_in[3];
    const float* bv = (const float*)d_in[4];
    const float* Wq = (const float*)d_in[5];
    const float* bq = (const float*)d_in[6];
    const float* Wk = (const float*)d_in[7];
    const float* bk = (const float*)d_in[8];
    const float* Wo = (const float*)d_in[9];
    const float* bo = (const float*)d_in[10];

    float* out   = (float*)d_out;
    float* out_i = out;                               // [2048]
    float* out_v = out + ED;                          // [8193, 2048]
    float* out_k = out_v + (size_t)L1 * ED;           // [8193, 2048]
    float* k_tail = out_k + (size_t)LCACHE * ED;
    float* v_tail = out_v + (size_t)LCACHE * ED;
    const float scale = 0.08838834764831845f;

    proj_kernel<<<384, 256>>>(x, Wq, bq, Wk, bk, Wv, bv, k_tail, v_tail);
    score_copyk_kernel<<<256, 512>>>(k, out_k, scale);
    tail_kernel<<<16, 128>>>(k_tail, v_tail, scale);
    av_copyv_kernel<<<256, 512>>>(v, out_v);
    out_proj_kernel<<<128, 256>>>(Wo, bo, out_i);
}

// round 9
// speedup vs baseline: 2.5624x; 1.0604x over previous
#include <cuda_runtime.h>

#define ED 2048
#define NH 16
#define HD 128
#define LCACHE 8192
#define L1 8193

// scratch (no allocs allowed)
__device__ float g_q[ED];
__device__ float g_hsum[NH];   // sum of exp(score) per head (unnormalized)
__device__ float g_vals[ED];   // sum of exp(score)*v per head-dim (unnormalized)

// ---------------------------------------------------------------------------
// Kernel 1: q = x@Wq + bq.  64 blocks x 512 threads, 32 cols/block.
// Warp reads 32 consecutive cols (128B full lines). Block 0 zeroes the
// g_hsum / g_vals accumulators for the fused kernel's atomics.
// ---------------------------------------------------------------------------
__global__ void __launch_bounds__(512, 4)
qproj_kernel(const float* __restrict__ x,
             const float* __restrict__ Wq, const float* __restrict__ bq) {
    __shared__ float sx[ED];
    __shared__ float red[16][32];
    int t = threadIdx.x;
    for (int i = t; i < ED; i += 512) sx[i] = x[i];
    if (blockIdx.x == 0) {
        if (t < NH) g_hsum[t] = 0.f;
        for (int i = t; i < ED; i += 512) g_vals[i] = 0.f;
    }
    __syncthreads();

    int jb = blockIdx.x * 32;
    int j  = jb + (t & 31);
    int isub = t >> 5;                    // 0..15
    float a0 = 0.f, a1 = 0.f, a2 = 0.f, a3 = 0.f;
    for (int i = isub; i < ED; i += 64) {
        a0 += sx[i]      * Wq[(size_t)i * ED + j];
        a1 += sx[i + 16] * Wq[(size_t)(i + 16) * ED + j];
        a2 += sx[i + 32] * Wq[(size_t)(i + 32) * ED + j];
        a3 += sx[i + 48] * Wq[(size_t)(i + 48) * ED + j];
    }
    red[isub][t & 31] = (a0 + a1) + (a2 + a3);
    __syncthreads();
    if (t < 32) {
        float r = bq[jb + t];
        #pragma unroll
        for (int s = 0; s < 16; ++s) r += red[s][t];
        g_q[jb + t] = r;
    }
}

// ---------------------------------------------------------------------------
// Kernel 2 (fused): 384 blocks x 512 threads.
//   blocks [0,256):  streaming attention over rows [0,8192):
//       read k row -> score -> copy to out_k; read v row -> acc exp(s)*v
//       -> copy to out_v.  Warp w owns head w (lane float4 = 4 of its 128
//       dims).  4-row batches with k+v loads issued together (8 LDG.128
//       in flight, two address streams).  Unnormalized softmax: per-warp
//       exp-sums -> g_hsum, weighted V partials -> g_vals (atomics).
//   blocks [256,384): k_i / v_i projection GEMVs (Wk, Wv), 32 cols each,
//       overlapped with the streaming traffic.
// ---------------------------------------------------------------------------
__global__ void __launch_bounds__(512, 2)
fused_kernel(const float* __restrict__ kc, const float* __restrict__ vc,
             const float* __restrict__ x,
             const float* __restrict__ Wk, const float* __restrict__ bk,
             const float* __restrict__ Wv, const float* __restrict__ bv,
             float* __restrict__ out_k, float* __restrict__ out_v,
             float* __restrict__ k_tail, float* __restrict__ v_tail,
             float scale) {
    __shared__ float sx[ED];
    __shared__ float red[16][32];
    int t = threadIdx.x;

    if (blockIdx.x < 256) {
        // ---------------- streaming attention + KV copy ----------------
        int lane = t & 31;
        int h = t >> 5;
        int l0 = blockIdx.x * 32;

        float4 q = ((const float4*)g_q)[t];
        const float4* ks = (const float4*)(kc + (size_t)l0 * ED);
        const float4* vs = (const float4*)(vc + (size_t)l0 * ED);
        float4* kd = (float4*)(out_k + (size_t)l0 * ED);
        float4* vd = (float4*)(out_v + (size_t)l0 * ED);

        float lsum = 0.f;
        float cx = 0.f, cy = 0.f, cz = 0.f, cw = 0.f;
        #pragma unroll
        for (int r0 = 0; r0 < 32; r0 += 4) {
            float4 a[4], b[4];
            #pragma unroll
            for (int u = 0; u < 4; ++u) a[u] = __ldcs(&ks[(r0 + u) * 512 + t]);
            #pragma unroll
            for (int u = 0; u < 4; ++u) b[u] = __ldcs(&vs[(r0 + u) * 512 + t]);
            #pragma unroll
            for (int u = 0; u < 4; ++u) __stcs(&kd[(r0 + u) * 512 + t], a[u]);
            float d[4];
            #pragma unroll
            for (int u = 0; u < 4; ++u)
                d[u] = a[u].x * q.x + a[u].y * q.y + a[u].z * q.z + a[u].w * q.w;
            #pragma unroll
            for (int off = 16; off; off >>= 1) {
                #pragma unroll
                for (int u = 0; u < 4; ++u)
                    d[u] += __shfl_xor_sync(0xffffffff, d[u], off);
            }
            #pragma unroll
            for (int u = 0; u < 4; ++u) __stcs(&vd[(r0 + u) * 512 + t], b[u]);
            #pragma unroll
            for (int u = 0; u < 4; ++u) {
                float p = expf(d[u] * scale);   // all lanes hold full dot
                lsum += p;
                cx += p * b[u].x;
                cy += p * b[u].y;
                cz += p * b[u].z;
                cw += p * b[u].w;
            }
        }
        if (lane == 0) atomicAdd(&g_hsum[h], lsum * 0.25f);
        else if (lane == 1) atomicAdd(&g_hsum[h], lsum * 0.25f);
        else if (lane == 2) atomicAdd(&g_hsum[h], lsum * 0.25f);
        else if (lane == 3) atomicAdd(&g_hsum[h], lsum * 0.25f);
        int c = 4 * t;
        atomicAdd(&g_vals[c],     cx);
        atomicAdd(&g_vals[c + 1], cy);
        atomicAdd(&g_vals[c + 2], cz);
        atomicAdd(&g_vals[c + 3], cw);
    } else {
        // ---------------- k_i / v_i projections (overlapped) ----------------
        int b2 = blockIdx.x - 256;           // 0..127
        int m  = b2 >> 6;                    // 0 = k, 1 = v
        int jb = (b2 & 63) * 32;
        const float* W  = m ? Wv : Wk;
        const float* bb = m ? bv : bk;
        float* dst      = m ? v_tail : k_tail;

        for (int i = t; i < ED; i += 512) sx[i] = x[i];
        __syncthreads();

        int j = jb + (t & 31);
        int isub = t >> 5;
        float a0 = 0.f, a1 = 0.f, a2 = 0.f, a3 = 0.f;
        for (int i = isub; i < ED; i += 64) {
            a0 += sx[i]      * W[(size_t)i * ED + j];
            a1 += sx[i + 16] * W[(size_t)(i + 16) * ED + j];
            a2 += sx[i + 32] * W[(size_t)(i + 32) * ED + j];
            a3 += sx[i + 48] * W[(size_t)(i + 48) * ED + j];
        }
        red[isub][t & 31] = (a0 + a1) + (a2 + a3);
        __syncthreads();
        if (t < 32) {
            float r = bb[jb + t];
            #pragma unroll
            for (int s = 0; s < 16; ++s) r += red[s][t];
            dst[jb + t] = r;
        }
    }
}

// ---------------------------------------------------------------------------
// Kernel 3 (tiny): appended row l=8192 per head. Adds exp(s_tail) to g_hsum
// and exp(s_tail)*v_tail into g_vals.  16 blocks x 128 threads.
// ---------------------------------------------------------------------------
__global__ void tail_kernel(const float* __restrict__ k_tail,
                            const float* __restrict__ v_tail,
                            float scale) {
    int h = blockIdx.x, t = threadIdx.x;
    __shared__ float red[128];
    __shared__ float s_e;
    red[t] = g_q[h * HD + t] * k_tail[h * HD + t];
    __syncthreads();
    #pragma unroll
    for (int o = 64; o; o >>= 1) {
        if (t < o) red[t] += red[t + o];
        __syncthreads();
    }
    if (t == 0) {
        float e = expf(red[0] * scale);
        g_hsum[h] += e;
        s_e = e;
    }
    __syncthreads();
    g_vals[h * HD + t] += s_e * v_tail[h * HD + t];
}

// ---------------------------------------------------------------------------
// Kernel 4: out_i = (g_vals / g_hsum[head]) @ Wo + bo.
// 64 blocks x 512 threads, 32 cols/block.
// ---------------------------------------------------------------------------
__global__ void __launch_bounds__(512, 4)
out_proj_kernel(const float* __restrict__ Wo,
                const float* __restrict__ bo,
                float* __restrict__ out_i) {
    __shared__ float sx[ED];
    __shared__ float red[16][32];
    __shared__ float sinv[NH];
    int t = threadIdx.x;
    if (t < NH) sinv[t] = 1.f / g_hsum[t];
    __syncthreads();
    for (int i = t; i < ED; i += 512) sx[i] = g_vals[i] * sinv[i >> 7];
    __syncthreads();

    int jb = blockIdx.x * 32;
    int j  = jb + (t & 31);
    int isub = t >> 5;
    float a0 = 0.f, a1 = 0.f, a2 = 0.f, a3 = 0.f;
    for (int i = isub; i < ED; i += 64) {
        a0 += sx[i]      * Wo[(size_t)i * ED + j];
        a1 += sx[i + 16] * Wo[(size_t)(i + 16) * ED + j];
        a2 += sx[i + 32] * Wo[(size_t)(i + 32) * ED + j];
        a3 += sx[i + 48] * Wo[(size_t)(i + 48) * ED + j];
    }
    red[isub][t & 31] = (a0 + a1) + (a2 + a3);
    __syncthreads();
    if (t < 32) {
        float r = bo[jb + t];
        #pragma unroll
        for (int s = 0; s < 16; ++s) r += red[s][t];
        out_i[jb + t] = r;
    }
}

extern "C" void kernel_launch(void* const* d_in, const int* in_sizes, int n_in,
                              void* d_out, int out_size) {
    const float* x  = (const float*)d_in[0];
    const float* v  = (const float*)d_in[1];
    const float* k  = (const float*)d_in[2];
    const float* Wv = (const float*)d_in[3];
    const float* bv = (const float*)d_in[4];
    const float* Wq = (const float*)d_in[5];
    const float* bq = (const float*)d_in[6];
    const float* Wk = (const float*)d_in[7];
    const float* bk = (const float*)d_in[8];
    const float* Wo = (const float*)d_in[9];
    const float* bo = (const float*)d_in[10];

    float* out   = (float*)d_out;
    float* out_i = out;                               // [2048]
    float* out_v = out + ED;                          // [8193, 2048]
    float* out_k = out_v + (size_t)L1 * ED;           // [8193, 2048]
    float* k_tail = out_k + (size_t)LCACHE * ED;
    float* v_tail = out_v + (size_t)LCACHE * ED;
    const float scale = 0.08838834764831845f;

    qproj_kernel<<<64, 512>>>(x, Wq, bq);
    fused_kernel<<<384, 512>>>(k, v, x, Wk, bk, Wv, bv,
                               out_k, out_v, k_tail, v_tail, scale);
    tail_kernel<<<16, 128>>>(k_tail, v_tail, scale);
    out_proj_kernel<<<64, 512>>>(Wo, bo, out_i);
}

// round 10
// speedup vs baseline: 3.2778x; 1.2792x over previous
#include <cuda_runtime.h>

#define ED 2048
#define EDV 512          // float4s per row
#define NH 16
#define HD 128
#define LCACHE 8192
#define L1 8193
#define NSLICE 8         // GEMV row-slices
#define SLICE_ROWS 256   // ED / NSLICE

// scratch (no allocs allowed)
__device__ float4 g_qpart[NSLICE * EDV];  // q partial sums per row-slice
__device__ float g_hsum[NH];              // sum of exp(score) per head
__device__ float g_vals[ED];              // sum of exp(score)*v (unnormalized)

// ---------------------------------------------------------------------------
// Kernel 1: q partial GEMV.  256 blocks x 512 threads.
// Block = (row-slice bi of 256 rows) x (col-group bj of 64 cols).
// Thread owns 4 consecutive cols (float4 weight loads), 8 rows -> 8
// independent LDG.128 in flight.  Partials to g_qpart; fused kernel sums.
// Block 0 zeroes the attention accumulators.
// ---------------------------------------------------------------------------
__global__ void __launch_bounds__(512, 2)
qproj_part_kernel(const float* __restrict__ x, const float* __restrict__ Wq) {
    __shared__ float sxs[SLICE_ROWS];
    __shared__ float4 red[32][16];
    int t = threadIdx.x;
    int bi = blockIdx.x >> 5;            // 0..7
    int bj = blockIdx.x & 31;            // 0..31
    int i0 = bi * SLICE_ROWS;

    if (blockIdx.x == 0) {
        if (t < NH) g_hsum[t] = 0.f;
        for (int i = t; i < ED; i += 512) g_vals[i] = 0.f;
    }
    if (t < SLICE_ROWS) sxs[t] = x[i0 + t];
    __syncthreads();

    int jq = t & 15;                     // float4 col within group
    int isub = t >> 4;                   // 0..31
    int jv = bj * 16 + jq;
    const float4* W4 = (const float4*)Wq;
    int rbase = isub * 8;

    float4 acc = make_float4(0.f, 0.f, 0.f, 0.f);
    #pragma unroll
    for (int r = 0; r < 8; ++r) {
        float s = sxs[rbase + r];
        float4 w = __ldcs(&W4[(size_t)(i0 + rbase + r) * EDV + jv]);
        acc.x += s * w.x; acc.y += s * w.y; acc.z += s * w.z; acc.w += s * w.w;
    }
    red[isub][jq] = acc;
    __syncthreads();
    if (t < 16) {
        float4 s = red[0][t];
        #pragma unroll
        for (int u = 1; u < 32; ++u) {
            s.x += red[u][t].x; s.y += red[u][t].y;
            s.z += red[u][t].z; s.w += red[u][t].w;
        }
        g_qpart[bi * EDV + bj * 16 + t] = s;
    }
}

// ---------------------------------------------------------------------------
// Kernel 2 (fused): 256 blocks x 512 threads, single wave at occ 2.
//   blocks [0,128):   k_i / v_i projection GEMVs (Wk, Wv), 32 cols each.
//   blocks [128,256): streaming attention over 64 rows each:
//       read k row -> score -> copy out_k; read v row -> acc exp(s)*v,
//       copy out_v.  Warp w == head w.  q assembled from g_qpart + bq.
//       Unnormalized softmax accumulators via atomics.
// ---------------------------------------------------------------------------
__global__ void __launch_bounds__(512, 2)
fused_kernel(const float* __restrict__ kc, const float* __restrict__ vc,
             const float* __restrict__ x,  const float* __restrict__ bq,
             const float* __restrict__ Wk, const float* __restrict__ bk,
             const float* __restrict__ Wv, const float* __restrict__ bv,
             float* __restrict__ out_k, float* __restrict__ out_v,
             float* __restrict__ k_tail, float* __restrict__ v_tail,
             float scale) {
    __shared__ float sx[ED];
    __shared__ float red[16][32];
    int t = threadIdx.x;

    if (blockIdx.x >= 128) {
        // ---------------- streaming attention + KV copy ----------------
        int lane = t & 31;
        int h = t >> 5;
        int l0 = (blockIdx.x - 128) * 64;

        float4 q = ((const float4*)bq)[t];
        #pragma unroll
        for (int s = 0; s < NSLICE; ++s) {
            float4 p = g_qpart[s * EDV + t];
            q.x += p.x; q.y += p.y; q.z += p.z; q.w += p.w;
        }

        const float4* ks = (const float4*)(kc + (size_t)l0 * ED);
        const float4* vs = (const float4*)(vc + (size_t)l0 * ED);
        float4* kd = (float4*)(out_k + (size_t)l0 * ED);
        float4* vd = (float4*)(out_v + (size_t)l0 * ED);

        float lsum = 0.f;
        float cx = 0.f, cy = 0.f, cz = 0.f, cw = 0.f;
        for (int r0 = 0; r0 < 64; r0 += 4) {
            float4 a[4], b[4];
            #pragma unroll
            for (int u = 0; u < 4; ++u) a[u] = __ldcs(&ks[(r0 + u) * EDV + t]);
            #pragma unroll
            for (int u = 0; u < 4; ++u) b[u] = __ldcs(&vs[(r0 + u) * EDV + t]);
            #pragma unroll
            for (int u = 0; u < 4; ++u) __stcs(&kd[(r0 + u) * EDV + t], a[u]);
            float d[4];
            #pragma unroll
            for (int u = 0; u < 4; ++u)
                d[u] = a[u].x * q.x + a[u].y * q.y + a[u].z * q.z + a[u].w * q.w;
            #pragma unroll
            for (int off = 16; off; off >>= 1) {
                #pragma unroll
                for (int u = 0; u < 4; ++u)
                    d[u] += __shfl_xor_sync(0xffffffff, d[u], off);
            }
            #pragma unroll
            for (int u = 0; u < 4; ++u) __stcs(&vd[(r0 + u) * EDV + t], b[u]);
            #pragma unroll
            for (int u = 0; u < 4; ++u) {
                float p = expf(d[u] * scale);   // all lanes hold full dot
                lsum += p;
                cx += p * b[u].x;
                cy += p * b[u].y;
                cz += p * b[u].z;
                cw += p * b[u].w;
            }
        }
        if (lane == 0) atomicAdd(&g_hsum[h], lsum);
        int c = 4 * t;
        atomicAdd(&g_vals[c],     cx);
        atomicAdd(&g_vals[c + 1], cy);
        atomicAdd(&g_vals[c + 2], cz);
        atomicAdd(&g_vals[c + 3], cw);
    } else {
        // ---------------- k_i / v_i projections (overlapped) ----------------
        int b2 = blockIdx.x;                 // 0..127
        int m  = b2 >> 6;                    // 0 = k, 1 = v
        int jb = (b2 & 63) * 32;
        const float* W  = m ? Wv : Wk;
        const float* bb = m ? bv : bk;
        float* dst      = m ? v_tail : k_tail;

        for (int i = t; i < ED; i += 512) sx[i] = x[i];
        __syncthreads();

        int j = jb + (t & 31);
        int isub = t >> 5;
        float a0 = 0.f, a1 = 0.f, a2 = 0.f, a3 = 0.f;
        for (int i = isub; i < ED; i += 64) {
            a0 += sx[i]      * W[(size_t)i * ED + j];
            a1 += sx[i + 16] * W[(size_t)(i + 16) * ED + j];
            a2 += sx[i + 32] * W[(size_t)(i + 32) * ED + j];
            a3 += sx[i + 48] * W[(size_t)(i + 48) * ED + j];
        }
        red[isub][t & 31] = (a0 + a1) + (a2 + a3);
        __syncthreads();
        if (t < 32) {
            float r = bb[jb + t];
            #pragma unroll
            for (int s = 0; s < 16; ++s) r += red[s][t];
            dst[jb + t] = r;
        }
    }
}

// ---------------------------------------------------------------------------
// Kernel 3 (tiny): appended row l=8192 per head: adds exp(s_tail) to g_hsum
// and exp(s_tail)*v_tail into g_vals.  Also seeds out_i with the bias bo
// (kernel 4 atomically accumulates on top).  16 blocks x 128 threads.
// ---------------------------------------------------------------------------
__global__ void tail_kernel(const float* __restrict__ k_tail,
                            const float* __restrict__ v_tail,
                            const float* __restrict__ bq,
                            const float* __restrict__ bo,
                            float* __restrict__ out_i,
                            float scale) {
    int h = blockIdx.x, t = threadIdx.x;
    __shared__ float red[128];
    __shared__ float s_e;
    int g = h * HD + t;
    float qv = bq[g];
    #pragma unroll
    for (int s = 0; s < NSLICE; ++s)
        qv += ((const float*)g_qpart)[s * ED + g];
    red[t] = qv * k_tail[g];
    __syncthreads();
    #pragma unroll
    for (int o = 64; o; o >>= 1) {
        if (t < o) red[t] += red[t + o];
        __syncthreads();
    }
    if (t == 0) {
        float e = expf(red[0] * scale);
        g_hsum[h] += e;
        s_e = e;
    }
    __syncthreads();
    g_vals[g] += s_e * v_tail[g];
    out_i[g] = bo[g];
}

// ---------------------------------------------------------------------------
// Kernel 4: out_i += (g_vals / g_hsum[head]) @ Wo.  Same 2-D split as
// kernel 1; per-block 64-col partials land in out_i via atomicAdd
// (8 contenders per address).  256 blocks x 512 threads.
// ---------------------------------------------------------------------------
__global__ void __launch_bounds__(512, 2)
oproj_part_kernel(const float* __restrict__ Wo, float* __restrict__ out_i) {
    __shared__ float sinv[NH];
    __shared__ float sxs[SLICE_ROWS];
    __shared__ float4 red[32][16];
    int t = threadIdx.x;
    int bi = blockIdx.x >> 5;
    int bj = blockIdx.x & 31;
    int i0 = bi * SLICE_ROWS;

    if (t < NH) sinv[t] = 1.f / g_hsum[t];
    __syncthreads();
    if (t < SLICE_ROWS) {
        int gi = i0 + t;
        sxs[t] = g_vals[gi] * sinv[gi >> 7];
    }
    __syncthreads();

    int jq = t & 15;
    int isub = t >> 4;
    int jv = bj * 16 + jq;
    const float4* W4 = (const float4*)Wo;
    int rbase = isub * 8;

    float4 acc = make_float4(0.f, 0.f, 0.f, 0.f);
    #pragma unroll
    for (int r = 0; r < 8; ++r) {
        float s = sxs[rbase + r];
        float4 w = __ldcs(&W4[(size_t)(i0 + rbase + r) * EDV + jv]);
        acc.x += s * w.x; acc.y += s * w.y; acc.z += s * w.z; acc.w += s * w.w;
    }
    red[isub][jq] = acc;
    __syncthreads();
    if (t < 16) {
        float4 s = red[0][t];
        #pragma unroll
        for (int u = 1; u < 32; ++u) {
            s.x += red[u][t].x; s.y += red[u][t].y;
            s.z += red[u][t].z; s.w += red[u][t].w;
        }
        int j = bj * 64 + t * 4;
        atomicAdd(&out_i[j],     s.x);
        atomicAdd(&out_i[j + 1], s.y);
        atomicAdd(&out_i[j + 2], s.z);
        atomicAdd(&out_i[j + 3], s.w);
    }
}

extern "C" void kernel_launch(void* const* d_in, const int* in_sizes, int n_in,
                              void* d_out, int out_size) {
    const float* x  = (const float*)d_in[0];
    const float* v  = (const float*)d_in[1];
    const float* k  = (const float*)d_in[2];
    const float* Wv = (const float*)d_in[3];
    const float* bv = (const float*)d_in[4];
    const float* Wq = (const float*)d_in[5];
    const float* bq = (const float*)d_in[6];
    const float* Wk = (const float*)d_in[7];
    const float* bk = (const float*)d_in[8];
    const float* Wo = (const float*)d_in[9];
    const float* bo = (const float*)d_in[10];

    float* out   = (float*)d_out;
    float* out_i = out;                               // [2048]
    float* out_v = out + ED;                          // [8193, 2048]
    float* out_k = out_v + (size_t)L1 * ED;           // [8193, 2048]
    float* k_tail = out_k + (size_t)LCACHE * ED;
    float* v_tail = out_v + (size_t)LCACHE * ED;
    const float scale = 0.08838834764831845f;

    qproj_part_kernel<<<256, 512>>>(x, Wq);
    fused_kernel<<<256, 512>>>(k, v, x, bq, Wk, bk, Wv, bv,
                               out_k, out_v, k_tail, v_tail, scale);
    tail_kernel<<<16, 128>>>(k_tail, v_tail, bq, bo, out_i, scale);
    oproj_part_kernel<<<256, 512>>>(Wo, out_i);
}

// round 11
// speedup vs baseline: 3.3009x; 1.0071x over previous
#include <cuda_runtime.h>

#define ED 2048
#define EDV 512          // float4s per row
#define NH 16
#define HD 128
#define LCACHE 8192
#define L1 8193

// scratch (no allocs allowed)
__device__ float g_q[ED];      // q = x@Wq + bq (final, incl. bias)
__device__ float g_hsum[NH];   // sum of exp(score) over rows [0,8192)
__device__ float g_sinv[NH];   // 1 / (g_hsum + exp(tail score))
__device__ float g_vals[ED];   // sum of exp(score)*v (unnormalized, incl. tail)
__device__ int   g_qdone;      // phase-A arrivals (stream blocks)
__device__ int   g_alldone;    // all-block arrivals (finisher election)

// ---------------------------------------------------------------------------
// Mega kernel: 256 blocks x 512 threads, occ 2 -> ALL blocks resident
// (256 < 2*148), so in-kernel spin joins are deadlock-free.
//
//  blocks [0,128):   k_i / v_i projection GEMVs (Wk, Wv), 32 cols each.
//                    Block 0 additionally seeds out_i = bo.
//  blocks [128,256): phase A: 16-col slice of q = x@Wq + bq -> g_q,
//                    arrive on g_qdone (fenced);
//                    phase B: spin until g_qdone==128, then stream 64 rows:
//                    read k row -> score -> copy out_k; read v row ->
//                    acc exp(s)*v -> copy out_v.  Warp w == head w.
//                    Unnormalized softmax accumulators via atomics.
//  All blocks arrive on g_alldone; the LAST block (sees 255) computes the
//  appended-row (l=8192) contribution, writes g_sinv, resets counters.
// ---------------------------------------------------------------------------
__global__ void __launch_bounds__(512, 2)
mega_kernel(const float* __restrict__ kc, const float* __restrict__ vc,
            const float* __restrict__ x,
            const float* __restrict__ Wq, const float* __restrict__ bq,
            const float* __restrict__ Wk, const float* __restrict__ bk,
            const float* __restrict__ Wv, const float* __restrict__ bv,
            const float* __restrict__ bo,
            float* __restrict__ out_k, float* __restrict__ out_v,
            float* __restrict__ k_tail, float* __restrict__ v_tail,
            float* __restrict__ out_i,
            float scale) {
    int t = threadIdx.x;

    if (blockIdx.x < 128) {
        // ---------------- k_i / v_i projections ----------------
        __shared__ float sx[ED];
        __shared__ float red[16][32];
        int b2 = blockIdx.x;                 // 0..127
        int m  = b2 >> 6;                    // 0 = k, 1 = v
        int jb = (b2 & 63) * 32;
        const float* W  = m ? Wv : Wk;
        const float* bb = m ? bv : bk;
        float* dst      = m ? v_tail : k_tail;

        if (b2 == 0)
            for (int i = t; i < ED; i += 512) out_i[i] = bo[i];

        for (int i = t; i < ED; i += 512) sx[i] = x[i];
        __syncthreads();

        int j = jb + (t & 31);
        int isub = t >> 5;
        float a0 = 0.f, a1 = 0.f, a2 = 0.f, a3 = 0.f;
        for (int i = isub; i < ED; i += 64) {
            a0 += sx[i]      * W[(size_t)i * ED + j];
            a1 += sx[i + 16] * W[(size_t)(i + 16) * ED + j];
            a2 += sx[i + 32] * W[(size_t)(i + 32) * ED + j];
            a3 += sx[i + 48] * W[(size_t)(i + 48) * ED + j];
        }
        red[isub][t & 31] = (a0 + a1) + (a2 + a3);
        __syncthreads();
        if (t < 32) {
            float r = bb[jb + t];
            #pragma unroll
            for (int s = 0; s < 16; ++s) r += red[s][t];
            dst[jb + t] = r;
        }
    } else {
        int sb = blockIdx.x - 128;           // 0..127

        // ---------------- phase A: q slice (16 cols, all 2048 rows) --------
        __shared__ float4 redq[128][4];
        {
            int jq = t & 3;                  // float4 col within 16-col group
            int rg = t >> 2;                 // 0..127, 16 rows each
            int jv = sb * 4 + jq;
            const float4* Wq4 = (const float4*)Wq;
            float4 acc = make_float4(0.f, 0.f, 0.f, 0.f);
            #pragma unroll
            for (int r = 0; r < 16; ++r) {
                int i = rg * 16 + r;
                float s = __ldg(&x[i]);
                float4 w = __ldcs(&Wq4[(size_t)i * EDV + jv]);
                acc.x += s * w.x; acc.y += s * w.y;
                acc.z += s * w.z; acc.w += s * w.w;
            }
            if (sb == 0) {                   // zero accumulators (pre-arrive)
                if (t < NH) g_hsum[t] = 0.f;
                for (int i = t; i < ED; i += 512) g_vals[i] = 0.f;
            }
            redq[rg][jq] = acc;
            __syncthreads();
            #pragma unroll
            for (int off = 64; off; off >>= 1) {
                if (rg < off) {
                    float4 o = redq[rg + off][jq];
                    float4 s = redq[rg][jq];
                    s.x += o.x; s.y += o.y; s.z += o.z; s.w += o.w;
                    redq[rg][jq] = s;
                }
                __syncthreads();
            }
            if (t < 4) {
                float4 s = redq[0][t];
                float4 b4 = ((const float4*)bq)[sb * 4 + t];
                s.x += b4.x; s.y += b4.y; s.z += b4.z; s.w += b4.w;
                ((float4*)g_q)[sb * 4 + t] = s;
            }
            __threadfence();
            __syncthreads();
            if (t == 0) atomicAdd(&g_qdone, 1);
        }

        // ---------------- phase B: wait for full q, then stream ------------
        if (t == 0) {
            while (*((volatile int*)&g_qdone) < 128) __nanosleep(64);
        }
        __syncthreads();
        __threadfence();

        int lane = t & 31;
        int h = t >> 5;
        int l0 = sb * 64;

        float4 q = ((const float4*)g_q)[t];
        const float4* ks = (const float4*)(kc + (size_t)l0 * ED);
        const float4* vs = (const float4*)(vc + (size_t)l0 * ED);
        float4* kd = (float4*)(out_k + (size_t)l0 * ED);
        float4* vd = (float4*)(out_v + (size_t)l0 * ED);

        float lsum = 0.f;
        float cx = 0.f, cy = 0.f, cz = 0.f, cw = 0.f;
        for (int r0 = 0; r0 < 64; r0 += 4) {
            float4 a[4], b[4];
            #pragma unroll
            for (int u = 0; u < 4; ++u) a[u] = __ldcs(&ks[(r0 + u) * EDV + t]);
            #pragma unroll
            for (int u = 0; u < 4; ++u) b[u] = __ldcs(&vs[(r0 + u) * EDV + t]);
            #pragma unroll
            for (int u = 0; u < 4; ++u) __stcs(&kd[(r0 + u) * EDV + t], a[u]);
            float d[4];
            #pragma unroll
            for (int u = 0; u < 4; ++u)
                d[u] = a[u].x * q.x + a[u].y * q.y + a[u].z * q.z + a[u].w * q.w;
            #pragma unroll
            for (int off = 16; off; off >>= 1) {
                #pragma unroll
                for (int u = 0; u < 4; ++u)
                    d[u] += __shfl_xor_sync(0xffffffff, d[u], off);
            }
            #pragma unroll
            for (int u = 0; u < 4; ++u) __stcs(&vd[(r0 + u) * EDV + t], b[u]);
            #pragma unroll
            for (int u = 0; u < 4; ++u) {
                float p = expf(d[u] * scale);   // all lanes hold full dot
                lsum += p;
                cx += p * b[u].x;
                cy += p * b[u].y;
                cz += p * b[u].z;
                cw += p * b[u].w;
            }
        }
        if (lane == 0) atomicAdd(&g_hsum[h], lsum);
        int c = 4 * t;
        atomicAdd(&g_vals[c],     cx);
        atomicAdd(&g_vals[c + 1], cy);
        atomicAdd(&g_vals[c + 2], cz);
        atomicAdd(&g_vals[c + 3], cw);
    }

    // ---------------- all-done join; last block handles the tail ----------
    __threadfence();
    __shared__ int s_last;
    __syncthreads();
    if (t == 0) s_last = atomicAdd(&g_alldone, 1);
    __syncthreads();
    if (s_last == 255) {
        // appended row l = 8192: score, exp, fold into g_vals, write g_sinv
        float4 qv = ((const float4*)g_q)[t];
        float4 kt = ((const float4*)k_tail)[t];
        float d = qv.x * kt.x + qv.y * kt.y + qv.z * kt.z + qv.w * kt.w;
        #pragma unroll
        for (int off = 16; off; off >>= 1)
            d += __shfl_xor_sync(0xffffffff, d, off);
        float e = expf(d * scale);          // all lanes of warp h hold e_h
        int h = t >> 5;                     // warp == head (512 thr, 16 warps)
        float4 vt = ((const float4*)v_tail)[t];
        float4 gv = ((float4*)g_vals)[t];
        gv.x += e * vt.x; gv.y += e * vt.y;
        gv.z += e * vt.z; gv.w += e * vt.w;
        ((float4*)g_vals)[t] = gv;
        if ((t & 31) == 0) g_sinv[h] = 1.f / (g_hsum[h] + e);
        if (t == 0) { g_qdone = 0; g_alldone = 0; }   // reset for graph replay
    }
}

// ---------------------------------------------------------------------------
// oproj: out_i += (g_vals * g_sinv[head]) @ Wo.  256 blocks x 512 threads;
// block = (row-slice of 256) x (64-col group); per-block partials land in
// out_i via atomicAdd (8 contenders per address; bias pre-seeded by mega).
// ---------------------------------------------------------------------------
__global__ void __launch_bounds__(512, 2)
oproj_part_kernel(const float* __restrict__ Wo, float* __restrict__ out_i) {
    __shared__ float ssinv[NH];
    __shared__ float sxs[256];
    __shared__ float4 red[32][16];
    int t = threadIdx.x;
    int bi = blockIdx.x >> 5;
    int bj = blockIdx.x & 31;
    int i0 = bi * 256;

    if (t < NH) ssinv[t] = g_sinv[t];
    __syncthreads();
    if (t < 256) {
        int gi = i0 + t;
        sxs[t] = g_vals[gi] * ssinv[gi >> 7];
    }
    __syncthreads();

    int jq = t & 15;
    int isub = t >> 4;
    int jv = bj * 16 + jq;
    const float4* W4 = (const float4*)Wo;
    int rbase = isub * 8;

    float4 acc = make_float4(0.f, 0.f, 0.f, 0.f);
    #pragma unroll
    for (int r = 0; r < 8; ++r) {
        float s = sxs[rbase + r];
        float4 w = __ldcs(&W4[(size_t)(i0 + rbase + r) * EDV + jv]);
        acc.x += s * w.x; acc.y += s * w.y; acc.z += s * w.z; acc.w += s * w.w;
    }
    red[isub][jq] = acc;
    __syncthreads();
    if (t < 16) {
        float4 s = red[0][t];
        #pragma unroll
        for (int u = 1; u < 32; ++u) {
            s.x += red[u][t].x; s.y += red[u][t].y;
            s.z += red[u][t].z; s.w += red[u][t].w;
        }
        int j = bj * 64 + t * 4;
        atomicAdd(&out_i[j],     s.x);
        atomicAdd(&out_i[j + 1], s.y);
        atomicAdd(&out_i[j + 2], s.z);
        atomicAdd(&out_i[j + 3], s.w);
    }
}

extern "C" void kernel_launch(void* const* d_in, const int* in_sizes, int n_in,
                              void* d_out, int out_size) {
    const float* x  = (const float*)d_in[0];
    const float* v  = (const float*)d_in[1];
    const float* k  = (const float*)d_in[2];
    const float* Wv = (const float*)d_in[3];
    const float* bv = (const float*)d_in[4];
    const float* Wq = (const float*)d_in[5];
    const float* bq = (const float*)d_in[6];
    const float* Wk = (const float*)d_in[7];
    const float* bk = (const float*)d_in[8];
    const float* Wo = (const float*)d_in[9];
    const float* bo = (const float*)d_in[10];

    float* out   = (float*)d_out;
    float* out_i = out;                               // [2048]
    float* out_v = out + ED;                          // [8193, 2048]
    float* out_k = out_v + (size_t)L1 * ED;           // [8193, 2048]
    float* k_tail = out_k + (size_t)LCACHE * ED;
    float* v_tail = out_v + (size_t)LCACHE * ED;
    const float scale = 0.08838834764831845f;

    mega_kernel<<<256, 512>>>(k, v, x, Wq, bq, Wk, bk, Wv, bv, bo,
                              out_k, out_v, k_tail, v_tail, out_i, scale);
    oproj_part_kernel<<<256, 512>>>(Wo, out_i);
}